// round 4
// baseline (speedup 1.0000x reference)
#include <cuda_runtime.h>
#include <math.h>

#define BATCH 4
#define NCLS 3
#define HH 96
#define WW 96
#define NPIX (HH * WW)           // 9216
#define NCOMBO 16                // batch(4) x class(2) x dir(2)
#define HCAP 2048                // in-smem histogram bins (d^2 < 2048); rest -> overflow
#define THREADS 256

typedef unsigned long long u64;

// cross-block state
__device__ float g_stats[NCOMBO][3];      // {max, mean, percentile}
__device__ int g_done = 0;                // last-block-done counter (reset each run)
__device__ int g_ovf_cnt[NCOMBO];
__device__ unsigned short g_ovf[NCOMBO][NPIX];  // overflow d^2 (expected unused)

// Dynamic smem layout:
//   int    hist[HCAP]          8192 B
//   ushort g[NPIX]            18432 B   (per-pixel 1-D column sq-dist of target)
//   u64    plo[96], phi[96]    1536 B   (pred-class-j column bitmasks, rows 0-63 / 64-95)
//   u64    llo[96], lhi[96]    1536 B   (label-class-j column bitmasks)
#define SMEM_BYTES (HCAP * 4 + NPIX * 2 + 4 * WW * 8)

// nearest |row delta| from row r to any set bit of the 96-bit column mask (lo,hi).
// returns >= 1000 if the column is empty.
__device__ __forceinline__ int col_dist(u64 lo, u64 hi, int r) {
    int down = 1000, up = 1000;
    if (r < 64) {
        u64 m = lo >> r;                      // bit k = row r+k
        if (m) down = __ffsll((long long)m) - 1;
        else if (hi) down = 64 - r + __ffsll((long long)hi) - 1;
        u64 mu = lo << (63 - r);              // row k<=r -> pos k+63-r
        if (mu) up = __clzll((long long)mu);
    } else {
        u64 m = hi >> (r - 64);
        if (m) down = __ffsll((long long)m) - 1;
        u64 mu = hi << (127 - r);             // row 64+k -> pos k+127-r
        if (mu) up = __clzll((long long)mu);
        else if (lo) up = (r - 63) + __clzll((long long)lo);
    }
    return min(down, up);
}

// ---------------------------------------------------------------------------
// One block per combo c: i = c>>2, class j = ((c>>1)&1)+1, dir = c&1
// dir 0 (fwd): source = pred mask, target = label mask; dir 1: swapped.
// Last finishing block assembles the 3x(3x5) output.
// ---------------------------------------------------------------------------
__global__ __launch_bounds__(THREADS, 1)
void hausdorff_kernel(const float* __restrict__ preds,
                      const int* __restrict__ labels,
                      float* __restrict__ out) {
    extern __shared__ char smem[];
    int* hist = (int*)smem;
    unsigned short* g = (unsigned short*)(hist + HCAP);
    u64* plo = (u64*)(g + NPIX);
    u64* phi = plo + WW;
    u64* llo = phi + WW;
    u64* lhi = llo + WW;

    __shared__ int s_n[THREADS];
    __shared__ float s_sum[THREADS];
    __shared__ int s_mx[THREADS];
    __shared__ int s_last;

    const int c = blockIdx.x;
    const int i = c >> 2;
    const int j = ((c >> 1) & 1) + 1;
    const int dir = c & 1;
    const int tid = threadIdx.x;
    const int lane = tid & 31;

    if (tid == 0) g_ovf_cnt[c] = 0;

    // zero histogram + bitmasks
    for (int k = tid; k < HCAP; k += THREADS) hist[k] = 0;
    if (tid < 4 * WW) plo[tid] = 0ull;   // zeroes plo,phi,llo,lhi (contiguous)
    __syncthreads();

    // build class-j column bitmasks (argmax of logits == argmax of softmax)
    {
        const float* base = preds + (size_t)i * NCLS * NPIX;
        const float4* b0 = (const float4*)base;
        const float4* b1 = (const float4*)(base + NPIX);
        const float4* b2 = (const float4*)(base + 2 * NPIX);
        const int4* l4 = (const int4*)(labels + i * NPIX);
        for (int q = tid; q < NPIX / 4; q += THREADS) {
            float4 a = __ldg(&b0[q]);
            float4 b = __ldg(&b1[q]);
            float4 d = __ldg(&b2[q]);
            int4 L = __ldg(&l4[q]);
            int p0 = q * 4;
            int row = p0 / WW;              // groups of 4 never cross a row (96%4==0)
            u64 bit = 1ull << (row & 63);
            u64* pm = (row < 64) ? plo : phi;
            u64* lm = (row < 64) ? llo : lhi;
            float av[4] = {a.x, a.y, a.z, a.w};
            float bv4[4] = {b.x, b.y, b.z, b.w};
            float dv[4] = {d.x, d.y, d.z, d.w};
            int lv[4] = {L.x, L.y, L.z, L.w};
            #pragma unroll
            for (int u = 0; u < 4; u++) {
                int pc = 0; float bv = av[u];
                if (bv4[u] > bv) { bv = bv4[u]; pc = 1; }
                if (dv[u] > bv) pc = 2;
                int col = (p0 & (WW - 1)) >= 0 ? (p0 - row * WW) + u : 0;
                if (pc == j) atomicOr(&pm[col], bit);
                if (lv[u] == j) atomicOr(&lm[col], bit);
            }
        }
    }
    __syncthreads();

    const u64* tlo = (dir == 0) ? llo : plo;   // target mask columns
    const u64* thi = (dir == 0) ? lhi : phi;
    const u64* slo = (dir == 0) ? plo : llo;   // source mask columns
    const u64* shi = (dir == 0) ? phi : lhi;

    // pass 1 (fully parallel): per-pixel 1-D column sq-dist to target
    for (int p = tid; p < NPIX; p += THREADS) {
        int r = p / WW;
        int cc = p - r * WW;
        int d = col_dist(tlo[cc], thi[cc], r);
        d = min(d, 255);
        g[p] = (unsigned short)(d * d);
    }
    __syncthreads();

    // pass 2: per source pixel, min over columns with outward pruning
    int mx_loc = 0;
    for (int p = tid; p < NPIX; p += THREADS) {
        int r = p / WW;
        int cc = p - r * WW;
        u64 sw = (r < 64) ? slo[cc] : shi[cc];
        bool valid = (sw >> (r & 63)) & 1ull;
        int best = 0x7fffffff;
        if (valid) {
            const unsigned short* grow = g + r * WW;
            best = grow[cc];
            for (int dc = 1; dc < WW; dc++) {
                int d2 = dc * dc;
                if (d2 >= best) break;
                int cl = cc - dc, cr = cc + dc;
                if (cl >= 0) { int v = d2 + (int)grow[cl]; if (v < best) best = v; }
                if (cr < WW) { int v = d2 + (int)grow[cr]; if (v < best) best = v; }
            }
        }
        // warp-aggregate the dominant d^2 == 0 bin
        unsigned zmask = __ballot_sync(0xffffffffu, valid && best == 0);
        if (lane == 0 && zmask) atomicAdd(&hist[0], __popc(zmask));
        if (valid && best > 0) {
            if (best < HCAP) {
                atomicAdd(&hist[best], 1);
                mx_loc = max(mx_loc, best);
            } else {
                int pos = atomicAdd(&g_ovf_cnt[c], 1);
                g_ovf[c][pos] = (unsigned short)min(best, 65535);
            }
        }
    }
    __syncthreads();

    // stats: deterministic tree reduction of n, sum(sqrt(d2)), max over hist
    int n_loc = 0;
    float sum_loc = 0.f;
    for (int b = tid; b < HCAP; b += THREADS) {
        int h = hist[b];
        n_loc += h;
        if (h) sum_loc += (float)h * sqrtf((float)b);
    }
    s_n[tid] = n_loc;
    s_sum[tid] = sum_loc;
    s_mx[tid] = mx_loc;
    __syncthreads();
    for (int off = THREADS / 2; off > 0; off >>= 1) {
        if (tid < off) {
            s_n[tid] += s_n[tid + off];
            s_sum[tid] += s_sum[tid + off];
            s_mx[tid] = max(s_mx[tid], s_mx[tid + off]);
        }
        __syncthreads();
    }

    if (tid == 0) {
        int n_hist = s_n[0];
        float sum = s_sum[0];
        int maxd2 = s_mx[0];
        int m = g_ovf_cnt[c];           // overflow entries (expected 0)
        if (m > 0) {                     // exact slow path, correctness only
            for (int a = 0; a < m - 1; a++) {
                int mi = a;
                for (int b = a + 1; b < m; b++)
                    if (g_ovf[c][b] < g_ovf[c][mi]) mi = b;
                unsigned short t = g_ovf[c][a];
                g_ovf[c][a] = g_ovf[c][mi];
                g_ovf[c][mi] = t;
            }
            for (int a = 0; a < m; a++) sum += sqrtf((float)g_ovf[c][a]);
        }
        int n = n_hist + m;
        float mx = 0.f, mean = 0.f, pcl = 0.f;
        if (n > 0) {
            int truemax = (m > 0) ? (int)g_ovf[c][m - 1] : maxd2;
            mx = sqrtf((float)truemax);
            mean = sum / (float)n;
            float pos = 0.95f * (float)(n - 1);
            int lo = (int)floorf(pos);
            int hi = (int)ceilf(pos);
            float frac = pos - (float)lo;
            float vlo = 0.f, vhi = 0.f;
            {
                int cum = 0;
                bool gotlo = false, gothi = false;
                for (int b = 0; b <= maxd2; b++) {
                    cum += hist[b];
                    if (!gotlo && cum > lo) { vlo = sqrtf((float)b); gotlo = true; }
                    if (cum > hi) { vhi = sqrtf((float)b); gothi = true; break; }
                }
                if (!gotlo) vlo = sqrtf((float)g_ovf[c][lo - n_hist]);
                if (!gothi) vhi = sqrtf((float)g_ovf[c][hi - n_hist]);
            }
            pcl = vlo * (1.0f - frac) + vhi * frac;
        }
        g_stats[c][0] = mx;
        g_stats[c][1] = mean;
        g_stats[c][2] = pcl;
        __threadfence();
        int t = atomicAdd(&g_done, 1);
        s_last = (t == NCOMBO - 1) ? 1 : 0;
    }
    __syncthreads();

    // last block assembles the output
    if (s_last && tid == 0) {
        __threadfence();
        g_done = 0;  // reset for next graph replay
        float M[3][5] = {{0}}, F[3][5] = {{0}}, R[3][5] = {{0}};
        for (int bi = 0; bi < BATCH; bi++) {
            for (int jj = 0; jj < 2; jj++) {
                int jc = jj + 1;
                int cf = (bi << 2) | (jj << 1);
                int cr = cf | 1;
                float fmx = g_stats[cf][0], rmx = g_stats[cr][0];
                float fme = g_stats[cf][1], rme = g_stats[cr][1];
                float fp  = g_stats[cf][2], rp  = g_stats[cr][2];
                F[0][jc] += fmx; R[0][jc] += rmx; M[0][jc] += fmaxf(fmx, rmx);
                F[1][jc] += fme; R[1][jc] += rme; M[1][jc] += fmaxf(fme, rme);
                // faithful to source bug: FHD gets both directions' percentiles,
                // RHD percentile row stays zero
                F[2][jc] += fp + rp;
                M[2][jc] += fmaxf(fp, rp);
            }
        }
        float* mats[3] = {&M[0][0], &F[0][0], &R[0][0]};
        for (int t2 = 0; t2 < 3; t2++) {
            float* X = mats[t2];
            for (int r = 0; r < 3; r++) {
                for (int c2 = 0; c2 < 3; c2++) X[r * 5 + c2] *= 0.25f;  // / batch
                X[r * 5 + 3] = (X[r * 5 + 0] + X[r * 5 + 1] + X[r * 5 + 2]) / 3.0f;
                X[r * 5 + 4] = (X[r * 5 + 1] + X[r * 5 + 2]) * 0.5f;
            }
            for (int k = 0; k < 15; k++) out[t2 * 15 + k] = X[k];
        }
    }
}

// ---------------------------------------------------------------------------
extern "C" void kernel_launch(void* const* d_in, const int* in_sizes, int n_in,
                              void* d_out, int out_size) {
    const float* preds = (const float*)d_in[0];
    const int* labels = (const int*)d_in[1];
    float* out = (float*)d_out;

    cudaFuncSetAttribute(hausdorff_kernel,
                         cudaFuncAttributeMaxDynamicSharedMemorySize, SMEM_BYTES);

    hausdorff_kernel<<<NCOMBO, THREADS, SMEM_BYTES>>>(preds, labels, out);
}

// round 5
// speedup vs baseline: 1.4663x; 1.4663x over previous
#include <cuda_runtime.h>
#include <math.h>

#define BATCH 4
#define NCLS 3
#define HH 96
#define WW 96
#define NPIX (HH * WW)           // 9216
#define NCOMBO 16                // batch(4) x class(2) x dir(2)
#define HCAP 2048                // in-smem histogram bins; d^2 >= HCAP -> overflow list
#define THREADS 256

// cross-block state
__device__ float g_stats[NCOMBO][3];           // {max, mean, percentile}
__device__ int g_done = 0;                     // last-block-done counter
__device__ int g_ovf_cnt[NCOMBO];
__device__ unsigned short g_ovf[NCOMBO][NPIX]; // overflow d^2 (expected unused)
__device__ unsigned char g_pred[BATCH][NPIX];  // argmax class map
__device__ unsigned char g_lab[BATCH][NPIX];   // label class map

// ---------------------------------------------------------------------------
// Kernel A: per-pixel argmax class + label byte maps (once per batch element)
// grid: BATCH * NPIX / (256*4) = 36 blocks
// ---------------------------------------------------------------------------
__global__ void build_maps_kernel(const float* __restrict__ preds,
                                  const int* __restrict__ labels) {
    int t = blockIdx.x * blockDim.x + threadIdx.x;   // one thread = 4 pixels
    const int QPB = NPIX / 4;                        // 2304 quads per batch elem
    if (t >= BATCH * QPB) return;
    int i = t / QPB;
    int q = t - i * QPB;

    const float* base = preds + (size_t)i * NCLS * NPIX;
    float4 a = __ldg((const float4*)base + q);
    float4 b = __ldg((const float4*)(base + NPIX) + q);
    float4 d = __ldg((const float4*)(base + 2 * NPIX) + q);
    int4 L = __ldg((const int4*)(labels + i * NPIX) + q);

    uchar4 pc, lb;
    {
        int k = 0; float bv = a.x;
        if (b.x > bv) { bv = b.x; k = 1; }
        if (d.x > bv) k = 2;
        pc.x = (unsigned char)k;
    }
    {
        int k = 0; float bv = a.y;
        if (b.y > bv) { bv = b.y; k = 1; }
        if (d.y > bv) k = 2;
        pc.y = (unsigned char)k;
    }
    {
        int k = 0; float bv = a.z;
        if (b.z > bv) { bv = b.z; k = 1; }
        if (d.z > bv) k = 2;
        pc.z = (unsigned char)k;
    }
    {
        int k = 0; float bv = a.w;
        if (b.w > bv) { bv = b.w; k = 1; }
        if (d.w > bv) k = 2;
        pc.w = (unsigned char)k;
    }
    lb.x = (unsigned char)L.x; lb.y = (unsigned char)L.y;
    lb.z = (unsigned char)L.z; lb.w = (unsigned char)L.w;
    *(uchar4*)&g_pred[i][q * 4] = pc;
    *(uchar4*)&g_lab[i][q * 4] = lb;
}

// ---------------------------------------------------------------------------
// Kernel B: one block per combo. c: i = c>>2, class j = ((c>>1)&1)+1, dir = c&1
// dir 0 (fwd): source = pred mask, target = label mask; dir 1: swapped.
// Last finishing block assembles the 3x(3x5) output.
//
// Dynamic smem layout:
//   int    hist[HCAP]    8192 B
//   ushort gF[NPIX]     18432 B   (fwd column sq-dist, then merged EDT)
//   ushort gB[NPIX]     18432 B   (bwd column sq-dist)
//   uchar  smapS[NPIX]   9216 B   (source class map)
//   uchar  tmapS[NPIX]   9216 B   (target class map)
// ---------------------------------------------------------------------------
#define SMEM_BYTES (HCAP * 4 + NPIX * 2 + NPIX * 2 + NPIX + NPIX)

__global__ __launch_bounds__(THREADS, 1)
void combo_kernel(float* __restrict__ out) {
    extern __shared__ char smem[];
    int* hist = (int*)smem;
    unsigned short* gF = (unsigned short*)(hist + HCAP);
    unsigned short* gB = gF + NPIX;
    unsigned char* smapS = (unsigned char*)(gB + NPIX);
    unsigned char* tmapS = smapS + NPIX;

    __shared__ int s_n[THREADS];
    __shared__ float s_sum[THREADS];
    __shared__ int s_mx[THREADS];
    __shared__ int s_last;

    const int c = blockIdx.x;
    const int i = c >> 2;
    const int j = ((c >> 1) & 1) + 1;
    const int dir = c & 1;
    const int tid = threadIdx.x;
    const int lane = tid & 31;

    if (tid == 0) g_ovf_cnt[c] = 0;

    // zero histogram (8 iters)
    for (int k = tid; k < HCAP; k += THREADS) hist[k] = 0;

    // copy byte maps from global (L2-hot, 18 KB) into smem, uint4 = 16 B/thread
    {
        const uint4* sm = (const uint4*)(dir == 0 ? g_pred[i] : g_lab[i]);
        const uint4* tm = (const uint4*)(dir == 0 ? g_lab[i] : g_pred[i]);
        uint4* ds = (uint4*)smapS;
        uint4* dt = (uint4*)tmapS;
        for (int q = tid; q < NPIX / 16; q += THREADS) {  // 576 -> 3 iters
            ds[q] = __ldg(&sm[q]);
            dt[q] = __ldg(&tm[q]);
        }
    }
    __syncthreads();

    // pass 1: per-column 1-D sq-dist; fwd (threads 0..95) and bwd (96..191)
    // run concurrently into separate arrays
    if (tid < WW) {
        const int col = tid;
        int last = -1000;
        #pragma unroll 4
        for (int r = 0; r < HH; r++) {
            if (tmapS[r * WW + col] == j) last = r;
            int d = min(r - last, 255);
            gF[r * WW + col] = (unsigned short)(d * d);
        }
    } else if (tid < 2 * WW) {
        const int col = tid - WW;
        int last = 1000;
        #pragma unroll 4
        for (int r = HH - 1; r >= 0; r--) {
            if (tmapS[r * WW + col] == j) last = r;
            int d = min(last - r, 255);
            gB[r * WW + col] = (unsigned short)(d * d);
        }
    }
    __syncthreads();

    // merge: gF = min(gF, gB), SIMD halfword (18 iters)
    {
        unsigned int* pf = (unsigned int*)gF;
        const unsigned int* pb = (const unsigned int*)gB;
        for (int q = tid; q < NPIX / 2; q += THREADS)
            pf[q] = __vminu2(pf[q], pb[q]);
    }
    __syncthreads();

    // pass 2: per source pixel, min over columns with outward pruning.
    // NPIX/THREADS = 36 full iterations -> warp-uniform loop, ballot legal.
    int mx_loc = 0;
    for (int p = tid; p < NPIX; p += THREADS) {
        bool valid = (smapS[p] == j);
        int best = 0x7fffffff;
        if (valid) {
            int r = p / WW;
            int cc = p - r * WW;
            const unsigned short* grow = gF + r * WW;
            best = grow[cc];
            for (int dc = 1; dc < WW; dc++) {
                int d2 = dc * dc;
                if (d2 >= best) break;
                int cl = cc - dc, cr = cc + dc;
                if (cl >= 0) { int v = d2 + (int)grow[cl]; if (v < best) best = v; }
                if (cr < WW) { int v = d2 + (int)grow[cr]; if (v < best) best = v; }
            }
        }
        // warp-aggregate the dominant d^2 == 0 bin
        unsigned zmask = __ballot_sync(0xffffffffu, valid && best == 0);
        if (lane == 0 && zmask) atomicAdd(&hist[0], __popc(zmask));
        if (valid && best > 0) {
            if (best < HCAP) {
                atomicAdd(&hist[best], 1);
                mx_loc = max(mx_loc, best);
            } else {
                int pos = atomicAdd(&g_ovf_cnt[c], 1);
                g_ovf[c][pos] = (unsigned short)min(best, 65535);
            }
        }
    }
    __syncthreads();

    // stats: deterministic tree reduction of n, sum(sqrt(d2)), max
    int n_loc = 0;
    float sum_loc = 0.f;
    for (int b = tid; b < HCAP; b += THREADS) {
        int h = hist[b];
        n_loc += h;
        if (h) sum_loc += (float)h * sqrtf((float)b);
    }
    s_n[tid] = n_loc;
    s_sum[tid] = sum_loc;
    s_mx[tid] = mx_loc;
    __syncthreads();
    for (int off = THREADS / 2; off > 0; off >>= 1) {
        if (tid < off) {
            s_n[tid] += s_n[tid + off];
            s_sum[tid] += s_sum[tid + off];
            s_mx[tid] = max(s_mx[tid], s_mx[tid + off]);
        }
        __syncthreads();
    }

    if (tid == 0) {
        int n_hist = s_n[0];
        float sum = s_sum[0];
        int maxd2 = s_mx[0];
        int m = g_ovf_cnt[c];           // overflow entries (expected 0)
        if (m > 0) {                     // exact slow path, correctness only
            for (int a = 0; a < m - 1; a++) {
                int mi = a;
                for (int b = a + 1; b < m; b++)
                    if (g_ovf[c][b] < g_ovf[c][mi]) mi = b;
                unsigned short t = g_ovf[c][a];
                g_ovf[c][a] = g_ovf[c][mi];
                g_ovf[c][mi] = t;
            }
            for (int a = 0; a < m; a++) sum += sqrtf((float)g_ovf[c][a]);
        }
        int n = n_hist + m;
        float mx = 0.f, mean = 0.f, pcl = 0.f;
        if (n > 0) {
            int truemax = (m > 0) ? (int)g_ovf[c][m - 1] : maxd2;
            mx = sqrtf((float)truemax);
            mean = sum / (float)n;
            float pos = 0.95f * (float)(n - 1);
            int lo = (int)floorf(pos);
            int hi = (int)ceilf(pos);
            float frac = pos - (float)lo;
            float vlo = 0.f, vhi = 0.f;
            {
                int cum = 0;
                bool gotlo = false, gothi = false;
                for (int b = 0; b <= maxd2; b++) {
                    cum += hist[b];
                    if (!gotlo && cum > lo) { vlo = sqrtf((float)b); gotlo = true; }
                    if (cum > hi) { vhi = sqrtf((float)b); gothi = true; break; }
                }
                if (!gotlo) vlo = sqrtf((float)g_ovf[c][lo - n_hist]);
                if (!gothi) vhi = sqrtf((float)g_ovf[c][hi - n_hist]);
            }
            pcl = vlo * (1.0f - frac) + vhi * frac;
        }
        g_stats[c][0] = mx;
        g_stats[c][1] = mean;
        g_stats[c][2] = pcl;
        __threadfence();
        int t = atomicAdd(&g_done, 1);
        s_last = (t == NCOMBO - 1) ? 1 : 0;
    }
    __syncthreads();

    // last block assembles the output
    if (s_last && tid == 0) {
        __threadfence();
        g_done = 0;  // reset for next graph replay
        float M[3][5] = {{0}}, F[3][5] = {{0}}, R[3][5] = {{0}};
        for (int bi = 0; bi < BATCH; bi++) {
            for (int jj = 0; jj < 2; jj++) {
                int jc = jj + 1;
                int cf = (bi << 2) | (jj << 1);
                int cr = cf | 1;
                float fmx = g_stats[cf][0], rmx = g_stats[cr][0];
                float fme = g_stats[cf][1], rme = g_stats[cr][1];
                float fp  = g_stats[cf][2], rp  = g_stats[cr][2];
                F[0][jc] += fmx; R[0][jc] += rmx; M[0][jc] += fmaxf(fmx, rmx);
                F[1][jc] += fme; R[1][jc] += rme; M[1][jc] += fmaxf(fme, rme);
                // faithful to source bug: FHD gets both directions' percentiles,
                // RHD percentile row stays zero
                F[2][jc] += fp + rp;
                M[2][jc] += fmaxf(fp, rp);
            }
        }
        float* mats[3] = {&M[0][0], &F[0][0], &R[0][0]};
        for (int t2 = 0; t2 < 3; t2++) {
            float* X = mats[t2];
            for (int r = 0; r < 3; r++) {
                for (int c2 = 0; c2 < 3; c2++) X[r * 5 + c2] *= 0.25f;  // / batch
                X[r * 5 + 3] = (X[r * 5 + 0] + X[r * 5 + 1] + X[r * 5 + 2]) / 3.0f;
                X[r * 5 + 4] = (X[r * 5 + 1] + X[r * 5 + 2]) * 0.5f;
            }
            for (int k = 0; k < 15; k++) out[t2 * 15 + k] = X[k];
        }
    }
}

// ---------------------------------------------------------------------------
extern "C" void kernel_launch(void* const* d_in, const int* in_sizes, int n_in,
                              void* d_out, int out_size) {
    const float* preds = (const float*)d_in[0];
    const int* labels = (const int*)d_in[1];
    float* out = (float*)d_out;

    cudaFuncSetAttribute(combo_kernel,
                         cudaFuncAttributeMaxDynamicSharedMemorySize, SMEM_BYTES);

    build_maps_kernel<<<(BATCH * NPIX / 4 + THREADS - 1) / THREADS, THREADS>>>(preds, labels);
    combo_kernel<<<NCOMBO, THREADS, SMEM_BYTES>>>(out);
}

// round 6
// speedup vs baseline: 2.0035x; 1.3663x over previous
#include <cuda_runtime.h>
#include <math.h>

#define BATCH 4
#define NCLS 3
#define HH 96
#define WW 96
#define NPIX (HH * WW)           // 9216
#define NCOMBO 16                // batch(4) x class(2) x dir(2)
#define HCAP 2048                // in-smem histogram bins; d^2 >= HCAP -> overflow list
#define THREADS 512
#define NWARP (THREADS / 32)

// cross-block state
__device__ float g_stats[NCOMBO][3];           // {max, mean, percentile}
__device__ int g_done = 0;                     // last-block-done counter
__device__ int g_ovf_cnt[NCOMBO];
__device__ unsigned short g_ovf[NCOMBO][NPIX]; // overflow d^2 (expected unused)
__device__ unsigned char g_pred[BATCH][NPIX];  // argmax class map
__device__ unsigned char g_lab[BATCH][NPIX];   // label class map

// ---------------------------------------------------------------------------
// Kernel A: per-pixel argmax class + label byte maps (once per batch element)
// ---------------------------------------------------------------------------
__global__ void build_maps_kernel(const float* __restrict__ preds,
                                  const int* __restrict__ labels) {
    int t = blockIdx.x * blockDim.x + threadIdx.x;   // one thread = 4 pixels
    const int QPB = NPIX / 4;                        // 2304 quads per batch elem
    if (t >= BATCH * QPB) return;
    int i = t / QPB;
    int q = t - i * QPB;

    const float* base = preds + (size_t)i * NCLS * NPIX;
    float4 a = __ldg((const float4*)base + q);
    float4 b = __ldg((const float4*)(base + NPIX) + q);
    float4 d = __ldg((const float4*)(base + 2 * NPIX) + q);
    int4 L = __ldg((const int4*)(labels + i * NPIX) + q);

    uchar4 pc, lb;
    {
        int k = 0; float bv = a.x;
        if (b.x > bv) { bv = b.x; k = 1; }
        if (d.x > bv) k = 2;
        pc.x = (unsigned char)k;
    }
    {
        int k = 0; float bv = a.y;
        if (b.y > bv) { bv = b.y; k = 1; }
        if (d.y > bv) k = 2;
        pc.y = (unsigned char)k;
    }
    {
        int k = 0; float bv = a.z;
        if (b.z > bv) { bv = b.z; k = 1; }
        if (d.z > bv) k = 2;
        pc.z = (unsigned char)k;
    }
    {
        int k = 0; float bv = a.w;
        if (b.w > bv) { bv = b.w; k = 1; }
        if (d.w > bv) k = 2;
        pc.w = (unsigned char)k;
    }
    lb.x = (unsigned char)L.x; lb.y = (unsigned char)L.y;
    lb.z = (unsigned char)L.z; lb.w = (unsigned char)L.w;
    *(uchar4*)&g_pred[i][q * 4] = pc;
    *(uchar4*)&g_lab[i][q * 4] = lb;
}

// ---------------------------------------------------------------------------
// Kernel B: one block per combo. c: i = c>>2, class j = ((c>>1)&1)+1, dir = c&1
// dir 0 (fwd): source = pred mask, target = label mask; dir 1: swapped.
// Last finishing block assembles the 3x(3x5) output.
//
// Dynamic smem layout:
//   int    hist[HCAP]      8192 B
//   ushort g[NPIX]        18432 B   (merged per-pixel column sq-dist)
//   uchar  gF[NPIX]        9216 B   (fwd raw dist, segmented)
//   uchar  gB[NPIX]        9216 B   (bwd raw dist, segmented)
//   uchar  smapS[NPIX]     9216 B
//   uchar  tmapS[NPIX]     9216 B
//   int    lastSet0[96]     384 B   (last set row in rows 0-47, -1000 if none)
//   int    firstSet1[96]    384 B   (first set row in rows 48-95, +1000 if none)
// ---------------------------------------------------------------------------
#define SMEM_BYTES (HCAP * 4 + NPIX * 2 + NPIX * 4 + 2 * WW * 4)

__global__ __launch_bounds__(THREADS, 1)
void combo_kernel(float* __restrict__ out) {
    extern __shared__ char smem[];
    int* hist = (int*)smem;
    unsigned short* g = (unsigned short*)(hist + HCAP);
    unsigned char* gF = (unsigned char*)(g + NPIX);
    unsigned char* gB = gF + NPIX;
    unsigned char* smapS = gB + NPIX;
    unsigned char* tmapS = smapS + NPIX;
    int* lastSet0 = (int*)(tmapS + NPIX);
    int* firstSet1 = lastSet0 + WW;

    __shared__ int s_n[NWARP];
    __shared__ float s_sum[NWARP];
    __shared__ int s_mx[NWARP];
    __shared__ int s_last;

    const int c = blockIdx.x;
    const int i = c >> 2;
    const int j = ((c >> 1) & 1) + 1;
    const int dir = c & 1;
    const int tid = threadIdx.x;
    const int lane = tid & 31;
    const int wid = tid >> 5;

    if (tid == 0) g_ovf_cnt[c] = 0;

    // zero histogram (4 iters)
    for (int k = tid; k < HCAP; k += THREADS) hist[k] = 0;

    // copy byte maps from global (L2-hot, 18 KB) into smem, uint4 = 16 B/thread
    {
        const uint4* sm = (const uint4*)(dir == 0 ? g_pred[i] : g_lab[i]);
        const uint4* tm = (const uint4*)(dir == 0 ? g_lab[i] : g_pred[i]);
        uint4* ds = (uint4*)smapS;
        uint4* dt = (uint4*)tmapS;
        for (int q = tid; q < NPIX / 16; q += THREADS) {  // 576 -> 2 iters
            ds[q] = __ldg(&sm[q]);
            dt[q] = __ldg(&tm[q]);
        }
    }
    __syncthreads();

    // pass 1: segmented per-column 1-D sweeps. 384 concurrent tasks:
    // task = (dirIdx in {fwd,bwd}) x (segment in {rows 0-47, rows 48-95}) x col
    // 48 serial iterations each. Boundary values fixed up in the merge pass.
    if (tid < 4 * WW) {
        const int col = tid % WW;
        const int seg = (tid / WW) & 1;
        const int dirIdx = tid / (2 * WW);
        const int r0 = seg * (HH / 2);
        if (dirIdx == 0) {              // forward (top -> down)
            int last = -1000;
            #pragma unroll 4
            for (int k = 0; k < HH / 2; k++) {
                int r = r0 + k;
                if (tmapS[r * WW + col] == j) last = r;
                gF[r * WW + col] = (unsigned char)min(r - last, 255);
            }
            if (seg == 0) lastSet0[col] = last;
        } else {                        // backward (bottom -> up)
            int first = 1000;
            #pragma unroll 4
            for (int k = HH / 2 - 1; k >= 0; k--) {
                int r = r0 + k;
                if (tmapS[r * WW + col] == j) first = r;
                gB[r * WW + col] = (unsigned char)min(first - r, 255);
            }
            if (seg == 1) firstSet1[col] = first;
        }
    }
    __syncthreads();

    // merge: exact 1-D column distance (with segment-boundary fix), squared
    for (int p = tid; p < NPIX; p += THREADS) {   // 18 iters
        int r = p / WW;
        int cc = p - r * WW;
        int d = min((int)gF[p], (int)gB[p]);
        if (r >= HH / 2) d = min(d, min(255, r - lastSet0[cc]));
        else             d = min(d, min(255, firstSet1[cc] - r));
        g[p] = (unsigned short)(d * d);
    }
    __syncthreads();

    // pass 2: per source pixel, min over columns with outward pruning.
    // NPIX/THREADS = 18 full iterations -> warp-uniform loop, match_any legal.
    int mx_loc = 0;
    for (int p = tid; p < NPIX; p += THREADS) {
        int r = p / WW;
        int cc = p - r * WW;
        bool valid = (smapS[p] == j);
        int best = -1;
        if (valid) {
            const unsigned short* grow = g + r * WW;
            best = grow[cc];
            for (int dc = 1; dc < WW; dc++) {
                int d2 = dc * dc;
                if (d2 >= best) break;
                int cl = cc - dc, cr = cc + dc;
                if (cl >= 0) { int v = d2 + (int)grow[cl]; if (v < best) best = v; }
                if (cr < WW) { int v = d2 + (int)grow[cr]; if (v < best) best = v; }
            }
        }
        // warp-aggregate equal bins: one atomic per distinct value per warp
        unsigned grp = __match_any_sync(0xffffffffu, best);
        if (valid) {
            if (best < HCAP) {
                if (lane == __ffs(grp) - 1) atomicAdd(&hist[best], __popc(grp));
                mx_loc = max(mx_loc, best);
            } else {
                int pos = atomicAdd(&g_ovf_cnt[c], 1);
                g_ovf[c][pos] = (unsigned short)min(best, 65535);
            }
        }
    }
    __syncthreads();

    // stats: n, sum(sqrt(d2)), max — shfl tree then cross-warp
    int n_loc = 0;
    float sum_loc = 0.f;
    for (int b = tid; b < HCAP; b += THREADS) {   // 4 iters
        int h = hist[b];
        n_loc += h;
        if (h) sum_loc += (float)h * sqrtf((float)b);
    }
    #pragma unroll
    for (int off = 16; off; off >>= 1) {
        n_loc += __shfl_down_sync(0xffffffffu, n_loc, off);
        sum_loc += __shfl_down_sync(0xffffffffu, sum_loc, off);
        mx_loc = max(mx_loc, __shfl_down_sync(0xffffffffu, mx_loc, off));
    }
    if (lane == 0) { s_n[wid] = n_loc; s_sum[wid] = sum_loc; s_mx[wid] = mx_loc; }
    __syncthreads();
    if (wid == 0) {
        int n2 = (lane < NWARP) ? s_n[lane] : 0;
        float sm2 = (lane < NWARP) ? s_sum[lane] : 0.f;
        int mx2 = (lane < NWARP) ? s_mx[lane] : 0;
        #pragma unroll
        for (int off = 8; off; off >>= 1) {
            n2 += __shfl_down_sync(0xffffffffu, n2, off);
            sm2 += __shfl_down_sync(0xffffffffu, sm2, off);
            mx2 = max(mx2, __shfl_down_sync(0xffffffffu, mx2, off));
        }
        if (lane == 0) { s_n[0] = n2; s_sum[0] = sm2; s_mx[0] = mx2; }
    }
    __syncthreads();

    if (tid == 0) {
        int n_hist = s_n[0];
        float sum = s_sum[0];
        int maxd2 = s_mx[0];
        int m = g_ovf_cnt[c];           // overflow entries (expected 0)
        if (m > 0) {                     // exact slow path, correctness only
            for (int a = 0; a < m - 1; a++) {
                int mi = a;
                for (int b = a + 1; b < m; b++)
                    if (g_ovf[c][b] < g_ovf[c][mi]) mi = b;
                unsigned short t = g_ovf[c][a];
                g_ovf[c][a] = g_ovf[c][mi];
                g_ovf[c][mi] = t;
            }
            for (int a = 0; a < m; a++) sum += sqrtf((float)g_ovf[c][a]);
        }
        int n = n_hist + m;
        float mx = 0.f, mean = 0.f, pcl = 0.f;
        if (n > 0) {
            int truemax = (m > 0) ? (int)g_ovf[c][m - 1] : maxd2;
            mx = sqrtf((float)truemax);
            mean = sum / (float)n;
            float pos = 0.95f * (float)(n - 1);
            int lo = (int)floorf(pos);
            int hi = (int)ceilf(pos);
            float frac = pos - (float)lo;
            float vlo = 0.f, vhi = 0.f;
            {
                int cum = 0;
                bool gotlo = false, gothi = false;
                for (int b = 0; b <= maxd2; b++) {
                    cum += hist[b];
                    if (!gotlo && cum > lo) { vlo = sqrtf((float)b); gotlo = true; }
                    if (cum > hi) { vhi = sqrtf((float)b); gothi = true; break; }
                }
                if (!gotlo) vlo = sqrtf((float)g_ovf[c][lo - n_hist]);
                if (!gothi) vhi = sqrtf((float)g_ovf[c][hi - n_hist]);
            }
            pcl = vlo * (1.0f - frac) + vhi * frac;
        }
        g_stats[c][0] = mx;
        g_stats[c][1] = mean;
        g_stats[c][2] = pcl;
        __threadfence();
        int t = atomicAdd(&g_done, 1);
        s_last = (t == NCOMBO - 1) ? 1 : 0;
    }
    __syncthreads();

    // last block assembles the output
    if (s_last && tid == 0) {
        __threadfence();
        g_done = 0;  // reset for next graph replay
        float M[3][5] = {{0}}, F[3][5] = {{0}}, R[3][5] = {{0}};
        for (int bi = 0; bi < BATCH; bi++) {
            for (int jj = 0; jj < 2; jj++) {
                int jc = jj + 1;
                int cf = (bi << 2) | (jj << 1);
                int cr = cf | 1;
                float fmx = g_stats[cf][0], rmx = g_stats[cr][0];
                float fme = g_stats[cf][1], rme = g_stats[cr][1];
                float fp  = g_stats[cf][2], rp  = g_stats[cr][2];
                F[0][jc] += fmx; R[0][jc] += rmx; M[0][jc] += fmaxf(fmx, rmx);
                F[1][jc] += fme; R[1][jc] += rme; M[1][jc] += fmaxf(fme, rme);
                // faithful to source bug: FHD gets both directions' percentiles,
                // RHD percentile row stays zero
                F[2][jc] += fp + rp;
                M[2][jc] += fmaxf(fp, rp);
            }
        }
        float* mats[3] = {&M[0][0], &F[0][0], &R[0][0]};
        for (int t2 = 0; t2 < 3; t2++) {
            float* X = mats[t2];
            for (int r = 0; r < 3; r++) {
                for (int c2 = 0; c2 < 3; c2++) X[r * 5 + c2] *= 0.25f;  // / batch
                X[r * 5 + 3] = (X[r * 5 + 0] + X[r * 5 + 1] + X[r * 5 + 2]) / 3.0f;
                X[r * 5 + 4] = (X[r * 5 + 1] + X[r * 5 + 2]) * 0.5f;
            }
            for (int k = 0; k < 15; k++) out[t2 * 15 + k] = X[k];
        }
    }
}

// ---------------------------------------------------------------------------
extern "C" void kernel_launch(void* const* d_in, const int* in_sizes, int n_in,
                              void* d_out, int out_size) {
    const float* preds = (const float*)d_in[0];
    const int* labels = (const int*)d_in[1];
    float* out = (float*)d_out;

    cudaFuncSetAttribute(combo_kernel,
                         cudaFuncAttributeMaxDynamicSharedMemorySize, SMEM_BYTES);

    build_maps_kernel<<<(BATCH * NPIX / 4 + 255) / 256, 256>>>(preds, labels);
    combo_kernel<<<NCOMBO, THREADS, SMEM_BYTES>>>(out);
}

// round 7
// speedup vs baseline: 2.1774x; 1.0868x over previous
#include <cuda_runtime.h>
#include <math.h>

#define BATCH 4
#define NCLS 3
#define HH 96
#define WW 96
#define NPIX (HH * WW)           // 9216
#define NCOMBO 16                // batch(4) x class(2) x dir(2)
#define HCAP 2048                // in-smem histogram bins; d^2 >= HCAP -> overflow list
#define THREADS 1024
#define NWARP (THREADS / 32)     // 32
#define NSEG 4
#define SEGROWS (HH / NSEG)      // 24

// cross-block state
__device__ float g_stats[NCOMBO][3];           // {max, mean, percentile}
__device__ int g_done = 0;                     // last-block-done counter
__device__ int g_ovf_cnt[NCOMBO];
__device__ unsigned short g_ovf[NCOMBO][NPIX]; // overflow d^2 (expected unused)
__device__ unsigned char g_pred[BATCH][NPIX];  // argmax class map
__device__ unsigned char g_lab[BATCH][NPIX];   // label class map

// ---------------------------------------------------------------------------
// Kernel A: per-pixel argmax class + label byte maps (once per batch element)
// ---------------------------------------------------------------------------
__global__ void build_maps_kernel(const float* __restrict__ preds,
                                  const int* __restrict__ labels) {
    int t = blockIdx.x * blockDim.x + threadIdx.x;   // one thread = 4 pixels
    const int QPB = NPIX / 4;                        // 2304 quads per batch elem
    if (t >= BATCH * QPB) return;
    int i = t / QPB;
    int q = t - i * QPB;

    const float* base = preds + (size_t)i * NCLS * NPIX;
    float4 a = __ldg((const float4*)base + q);
    float4 b = __ldg((const float4*)(base + NPIX) + q);
    float4 d = __ldg((const float4*)(base + 2 * NPIX) + q);
    int4 L = __ldg((const int4*)(labels + i * NPIX) + q);

    uchar4 pc, lb;
    {
        int k = 0; float bv = a.x;
        if (b.x > bv) { bv = b.x; k = 1; }
        if (d.x > bv) k = 2;
        pc.x = (unsigned char)k;
    }
    {
        int k = 0; float bv = a.y;
        if (b.y > bv) { bv = b.y; k = 1; }
        if (d.y > bv) k = 2;
        pc.y = (unsigned char)k;
    }
    {
        int k = 0; float bv = a.z;
        if (b.z > bv) { bv = b.z; k = 1; }
        if (d.z > bv) k = 2;
        pc.z = (unsigned char)k;
    }
    {
        int k = 0; float bv = a.w;
        if (b.w > bv) { bv = b.w; k = 1; }
        if (d.w > bv) k = 2;
        pc.w = (unsigned char)k;
    }
    lb.x = (unsigned char)L.x; lb.y = (unsigned char)L.y;
    lb.z = (unsigned char)L.z; lb.w = (unsigned char)L.w;
    *(uchar4*)&g_pred[i][q * 4] = pc;
    *(uchar4*)&g_lab[i][q * 4] = lb;
}

// ---------------------------------------------------------------------------
// Kernel B: one block per combo. c: i = c>>2, class j = ((c>>1)&1)+1, dir = c&1
// dir 0 (fwd): source = pred mask, target = label mask; dir 1: swapped.
// Last finishing block assembles the 3x(3x5) output.
//
// Dynamic smem layout:
//   int    hist[HCAP]         8192 B
//   ushort g[NPIX]           18432 B   (merged per-pixel column sq-dist)
//   uchar  gF[NPIX]           9216 B   (fwd raw dist, 4-segmented)
//   uchar  gB[NPIX]           9216 B   (bwd raw dist, 4-segmented)
//   uchar  smapS[NPIX]        9216 B
//   uchar  tmapS[NPIX]        9216 B
//   int    lastSet[4][96]     1536 B   (last set row within segment, -1000 if none)
//   int    firstSet[4][96]    1536 B   (first set row within segment, +1000 if none)
//   int    pmArr[4][96]       1536 B   (max lastSet over segments < s)
//   int    sfArr[4][96]       1536 B   (min firstSet over segments > s)
// ---------------------------------------------------------------------------
#define SMEM_BYTES (HCAP * 4 + NPIX * 2 + NPIX * 4 + 4 * NSEG * WW * 4)

__global__ __launch_bounds__(THREADS, 1)
void combo_kernel(float* __restrict__ out) {
    extern __shared__ char smem[];
    int* hist = (int*)smem;
    unsigned short* g = (unsigned short*)(hist + HCAP);
    unsigned char* gF = (unsigned char*)(g + NPIX);
    unsigned char* gB = gF + NPIX;
    unsigned char* smapS = gB + NPIX;
    unsigned char* tmapS = smapS + NPIX;
    int* lastSet = (int*)(tmapS + NPIX);       // [NSEG][WW]
    int* firstSet = lastSet + NSEG * WW;
    int* pmArr = firstSet + NSEG * WW;
    int* sfArr = pmArr + NSEG * WW;

    __shared__ int s_n[NWARP];
    __shared__ float s_sum[NWARP];
    __shared__ int s_mx[NWARP];
    __shared__ int s_last;

    const int c = blockIdx.x;
    const int i = c >> 2;
    const int j = ((c >> 1) & 1) + 1;
    const int dir = c & 1;
    const int tid = threadIdx.x;
    const int lane = tid & 31;
    const int wid = tid >> 5;

    if (tid == 0) g_ovf_cnt[c] = 0;

    // zero histogram (2 iters)
    for (int k = tid; k < HCAP; k += THREADS) hist[k] = 0;

    // copy byte maps from global (L2-hot, 18 KB) into smem, uint4 = 16 B/thread
    {
        const uint4* sm = (const uint4*)(dir == 0 ? g_pred[i] : g_lab[i]);
        const uint4* tm = (const uint4*)(dir == 0 ? g_lab[i] : g_pred[i]);
        uint4* ds = (uint4*)smapS;
        uint4* dt = (uint4*)tmapS;
        for (int q = tid; q < NPIX / 16; q += THREADS) {  // 576 -> 1 iter
            ds[q] = __ldg(&sm[q]);
            dt[q] = __ldg(&tm[q]);
        }
    }
    __syncthreads();

    // pass 1: 4-way segmented per-column 1-D sweeps.
    // 768 tasks = dir(2) x seg(4) x col(96), 24 serial iters each.
    if (tid < 2 * NSEG * WW) {
        const int col = tid % WW;
        const int seg = (tid / WW) & (NSEG - 1);
        const int dirIdx = tid / (NSEG * WW);
        const int r0 = seg * SEGROWS;
        if (dirIdx == 0) {              // forward (top -> down)
            int last = -1000;
            #pragma unroll 4
            for (int k = 0; k < SEGROWS; k++) {
                int r = r0 + k;
                if (tmapS[r * WW + col] == j) last = r;
                gF[r * WW + col] = (unsigned char)min(r - last, 255);
            }
            lastSet[seg * WW + col] = last;
        } else {                        // backward (bottom -> up)
            int first = 1000;
            #pragma unroll 4
            for (int k = SEGROWS - 1; k >= 0; k--) {
                int r = r0 + k;
                if (tmapS[r * WW + col] == j) first = r;
                gB[r * WW + col] = (unsigned char)min(first - r, 255);
            }
            firstSet[seg * WW + col] = first;
        }
    }
    __syncthreads();

    // per-column prefix-max of lastSet / suffix-min of firstSet (4 iters)
    if (tid < WW) {
        const int col = tid;
        int pm = -1000;
        #pragma unroll
        for (int s = 0; s < NSEG; s++) {
            pmArr[s * WW + col] = pm;
            pm = max(pm, lastSet[s * WW + col]);
        }
    } else if (tid < 2 * WW) {
        const int col = tid - WW;
        int fm = 1000;
        #pragma unroll
        for (int s = NSEG - 1; s >= 0; s--) {
            sfArr[s * WW + col] = fm;
            fm = min(fm, firstSet[s * WW + col]);
        }
    }
    __syncthreads();

    // merge: exact 1-D column distance with cross-segment fix, squared (9 iters)
    for (int p = tid; p < NPIX; p += THREADS) {
        int r = p / WW;
        int cc = p - r * WW;
        int s = r / SEGROWS;
        int d = min((int)gF[p], (int)gB[p]);
        d = min(d, r - pmArr[s * WW + cc]);
        d = min(d, sfArr[s * WW + cc] - r);
        d = min(d, 255);
        g[p] = (unsigned short)(d * d);
    }
    __syncthreads();

    // pass 2: per source pixel, min over columns. NPIX/THREADS = 9 exact
    // iterations -> warp-uniform loop, match_any legal.
    int mx_loc = 0;
    for (int p = tid; p < NPIX; p += THREADS) {
        int r = p / WW;
        int cc = p - r * WW;
        bool valid = (smapS[p] == j);
        int best = -1;
        if (valid) {
            const unsigned short* grow = g + r * WW;
            best = grow[cc];
            if (best > 1) {
                // unconditional window dc=1..3: addresses independent of best,
                // min(best, d2+g) is safe even when d2 >= best
                int v;
                v = 1 + ((cc - 1 >= 0) ? (int)grow[cc - 1] : 0x7fff); best = min(best, v);
                v = 1 + ((cc + 1 < WW) ? (int)grow[cc + 1] : 0x7fff); best = min(best, v);
                v = 4 + ((cc - 2 >= 0) ? (int)grow[cc - 2] : 0x7fff); best = min(best, v);
                v = 4 + ((cc + 2 < WW) ? (int)grow[cc + 2] : 0x7fff); best = min(best, v);
                v = 9 + ((cc - 3 >= 0) ? (int)grow[cc - 3] : 0x7fff); best = min(best, v);
                v = 9 + ((cc + 3 < WW) ? (int)grow[cc + 3] : 0x7fff); best = min(best, v);
                for (int dc = 4; dc < WW; dc++) {
                    int d2 = dc * dc;
                    if (d2 >= best) break;
                    int cl = cc - dc, cr = cc + dc;
                    if (cl >= 0) { int vv = d2 + (int)grow[cl]; if (vv < best) best = vv; }
                    if (cr < WW) { int vv = d2 + (int)grow[cr]; if (vv < best) best = vv; }
                }
            }
        }
        // warp-aggregate equal bins: one atomic per distinct value per warp
        unsigned grp = __match_any_sync(0xffffffffu, best);
        if (valid) {
            if (best < HCAP) {
                if (lane == __ffs(grp) - 1) atomicAdd(&hist[best], __popc(grp));
                mx_loc = max(mx_loc, best);
            } else {
                int pos = atomicAdd(&g_ovf_cnt[c], 1);
                g_ovf[c][pos] = (unsigned short)min(best, 65535);
            }
        }
    }
    __syncthreads();

    // stats: n, sum(sqrt(d2)), max — shfl tree then cross-warp
    int n_loc = 0;
    float sum_loc = 0.f;
    for (int b = tid; b < HCAP; b += THREADS) {   // 2 iters
        int h = hist[b];
        n_loc += h;
        if (h) sum_loc += (float)h * sqrtf((float)b);
    }
    #pragma unroll
    for (int off = 16; off; off >>= 1) {
        n_loc += __shfl_down_sync(0xffffffffu, n_loc, off);
        sum_loc += __shfl_down_sync(0xffffffffu, sum_loc, off);
        mx_loc = max(mx_loc, __shfl_down_sync(0xffffffffu, mx_loc, off));
    }
    if (lane == 0) { s_n[wid] = n_loc; s_sum[wid] = sum_loc; s_mx[wid] = mx_loc; }
    __syncthreads();
    if (wid == 0) {
        int n2 = s_n[lane];
        float sm2 = s_sum[lane];
        int mx2 = s_mx[lane];
        #pragma unroll
        for (int off = 16; off; off >>= 1) {
            n2 += __shfl_down_sync(0xffffffffu, n2, off);
            sm2 += __shfl_down_sync(0xffffffffu, sm2, off);
            mx2 = max(mx2, __shfl_down_sync(0xffffffffu, mx2, off));
        }
        if (lane == 0) { s_n[0] = n2; s_sum[0] = sm2; s_mx[0] = mx2; }
    }
    __syncthreads();

    if (tid == 0) {
        int n_hist = s_n[0];
        float sum = s_sum[0];
        int maxd2 = s_mx[0];
        int m = g_ovf_cnt[c];           // overflow entries (expected 0)
        if (m > 0) {                     // exact slow path, correctness only
            for (int a = 0; a < m - 1; a++) {
                int mi = a;
                for (int b = a + 1; b < m; b++)
                    if (g_ovf[c][b] < g_ovf[c][mi]) mi = b;
                unsigned short t = g_ovf[c][a];
                g_ovf[c][a] = g_ovf[c][mi];
                g_ovf[c][mi] = t;
            }
            for (int a = 0; a < m; a++) sum += sqrtf((float)g_ovf[c][a]);
        }
        int n = n_hist + m;
        float mx = 0.f, mean = 0.f, pcl = 0.f;
        if (n > 0) {
            int truemax = (m > 0) ? (int)g_ovf[c][m - 1] : maxd2;
            mx = sqrtf((float)truemax);
            mean = sum / (float)n;
            float pos = 0.95f * (float)(n - 1);
            int lo = (int)floorf(pos);
            int hi = (int)ceilf(pos);
            float frac = pos - (float)lo;
            float vlo = 0.f, vhi = 0.f;
            {
                int cum = 0;
                bool gotlo = false, gothi = false;
                for (int b = 0; b <= maxd2; b++) {
                    cum += hist[b];
                    if (!gotlo && cum > lo) { vlo = sqrtf((float)b); gotlo = true; }
                    if (cum > hi) { vhi = sqrtf((float)b); gothi = true; break; }
                }
                if (!gotlo) vlo = sqrtf((float)g_ovf[c][lo - n_hist]);
                if (!gothi) vhi = sqrtf((float)g_ovf[c][hi - n_hist]);
            }
            pcl = vlo * (1.0f - frac) + vhi * frac;
        }
        g_stats[c][0] = mx;
        g_stats[c][1] = mean;
        g_stats[c][2] = pcl;
        __threadfence();
        int t = atomicAdd(&g_done, 1);
        s_last = (t == NCOMBO - 1) ? 1 : 0;
    }
    __syncthreads();

    // last block assembles the output
    if (s_last && tid == 0) {
        __threadfence();
        g_done = 0;  // reset for next graph replay
        float M[3][5] = {{0}}, F[3][5] = {{0}}, R[3][5] = {{0}};
        for (int bi = 0; bi < BATCH; bi++) {
            for (int jj = 0; jj < 2; jj++) {
                int jc = jj + 1;
                int cf = (bi << 2) | (jj << 1);
                int cr = cf | 1;
                float fmx = g_stats[cf][0], rmx = g_stats[cr][0];
                float fme = g_stats[cf][1], rme = g_stats[cr][1];
                float fp  = g_stats[cf][2], rp  = g_stats[cr][2];
                F[0][jc] += fmx; R[0][jc] += rmx; M[0][jc] += fmaxf(fmx, rmx);
                F[1][jc] += fme; R[1][jc] += rme; M[1][jc] += fmaxf(fme, rme);
                // faithful to source bug: FHD gets both directions' percentiles,
                // RHD percentile row stays zero
                F[2][jc] += fp + rp;
                M[2][jc] += fmaxf(fp, rp);
            }
        }
        float* mats[3] = {&M[0][0], &F[0][0], &R[0][0]};
        for (int t2 = 0; t2 < 3; t2++) {
            float* X = mats[t2];
            for (int r = 0; r < 3; r++) {
                for (int c2 = 0; c2 < 3; c2++) X[r * 5 + c2] *= 0.25f;  // / batch
                X[r * 5 + 3] = (X[r * 5 + 0] + X[r * 5 + 1] + X[r * 5 + 2]) / 3.0f;
                X[r * 5 + 4] = (X[r * 5 + 1] + X[r * 5 + 2]) * 0.5f;
            }
            for (int k = 0; k < 15; k++) out[t2 * 15 + k] = X[k];
        }
    }
}

// ---------------------------------------------------------------------------
extern "C" void kernel_launch(void* const* d_in, const int* in_sizes, int n_in,
                              void* d_out, int out_size) {
    const float* preds = (const float*)d_in[0];
    const int* labels = (const int*)d_in[1];
    float* out = (float*)d_out;

    cudaFuncSetAttribute(combo_kernel,
                         cudaFuncAttributeMaxDynamicSharedMemorySize, SMEM_BYTES);

    build_maps_kernel<<<(BATCH * NPIX / 4 + 255) / 256, 256>>>(preds, labels);
    combo_kernel<<<NCOMBO, THREADS, SMEM_BYTES>>>(out);
}

// round 8
// speedup vs baseline: 2.2495x; 1.0331x over previous
#include <cuda_runtime.h>
#include <math.h>

#define BATCH 4
#define NCLS 3
#define HH 96
#define WW 96
#define NPIX (HH * WW)           // 9216
#define NCOMBO 16                // batch(4) x class(2) x dir(2)
#define HCAP 1024                // in-smem histogram bins; d^2 >= HCAP -> overflow list
#define THREADS 1024
#define NWARP (THREADS / 32)     // 32
#define NSEG 4
#define SEGROWS (HH / NSEG)      // 24
#define FULLMASK 0xffffffffu

// cross-block state
__device__ float g_stats[NCOMBO][3];           // {max, mean, percentile}
__device__ int g_done = 0;                     // last-block-done counter
__device__ int g_ovf_cnt[NCOMBO];
__device__ unsigned short g_ovf[NCOMBO][NPIX]; // overflow d^2 (expected unused)

// Dynamic smem layout (exactly 64 KB):
//   int    hist[HCAP]         4096 B
//   ushort g[NPIX]           18432 B   (merged per-pixel column sq-dist)
//   uchar  gF[NPIX]           9216 B   (fwd raw dist, 4-segmented)
//   uchar  gB[NPIX]           9216 B   (bwd raw dist, 4-segmented)
//   uchar  smapS[NPIX]        9216 B   (source class map)
//   uchar  tmapS[NPIX]        9216 B   (target class map)
//   int    lastSet[4][96]     1536 B
//   int    firstSet[4][96]    1536 B
//   int    pmArr[4][96]       1536 B
//   int    sfArr[4][96]       1536 B
#define SMEM_BYTES (HCAP * 4 + NPIX * 2 + NPIX * 4 + 4 * NSEG * WW * 4)

// ---------------------------------------------------------------------------
// Single fused kernel: one block per combo.
// c: i = c>>2, class j = ((c>>1)&1)+1, dir = c&1
// dir 0 (fwd): source = pred mask, target = label mask; dir 1: swapped.
// Last finishing block assembles the 3x(3x5) output.
// ---------------------------------------------------------------------------
__global__ __launch_bounds__(THREADS, 1)
void hausdorff_kernel(const float* __restrict__ preds,
                      const int* __restrict__ labels,
                      float* __restrict__ out) {
    extern __shared__ char smem[];
    int* hist = (int*)smem;
    unsigned short* g = (unsigned short*)(hist + HCAP);
    unsigned char* gF = (unsigned char*)(g + NPIX);
    unsigned char* gB = gF + NPIX;
    unsigned char* smapS = gB + NPIX;
    unsigned char* tmapS = smapS + NPIX;
    int* lastSet = (int*)(tmapS + NPIX);       // [NSEG][WW]
    int* firstSet = lastSet + NSEG * WW;
    int* pmArr = firstSet + NSEG * WW;
    int* sfArr = pmArr + NSEG * WW;

    __shared__ int s_n[NWARP];
    __shared__ float s_sum[NWARP];
    __shared__ int s_mx[NWARP];
    __shared__ int s_last;

    const int c = blockIdx.x;
    const int i = c >> 2;
    const int j = ((c >> 1) & 1) + 1;
    const int dir = c & 1;
    const int tid = threadIdx.x;
    const int lane = tid & 31;
    const int wid = tid >> 5;

    if (tid == 0) g_ovf_cnt[c] = 0;

    // zero histogram (1 iter)
    hist[tid] = 0;

    // fused map build: argmax class + label byte maps directly into smem
    // (argmax of logits == argmax of softmax). 2304 quads -> 3 strided iters.
    {
        const float* base = preds + (size_t)i * NCLS * NPIX;
        const float4* b0 = (const float4*)base;
        const float4* b1 = (const float4*)(base + NPIX);
        const float4* b2 = (const float4*)(base + 2 * NPIX);
        const int4* l4 = (const int4*)(labels + i * NPIX);
        unsigned char* pmap = (dir == 0) ? smapS : tmapS;  // pred map dest
        unsigned char* lmap = (dir == 0) ? tmapS : smapS;  // label map dest
        for (int q = tid; q < NPIX / 4; q += THREADS) {
            float4 a = __ldg(&b0[q]);
            float4 b = __ldg(&b1[q]);
            float4 d = __ldg(&b2[q]);
            int4 L = __ldg(&l4[q]);
            uchar4 pc, lb;
            {
                int k = 0; float bv = a.x;
                if (b.x > bv) { bv = b.x; k = 1; }
                if (d.x > bv) k = 2;
                pc.x = (unsigned char)k;
            }
            {
                int k = 0; float bv = a.y;
                if (b.y > bv) { bv = b.y; k = 1; }
                if (d.y > bv) k = 2;
                pc.y = (unsigned char)k;
            }
            {
                int k = 0; float bv = a.z;
                if (b.z > bv) { bv = b.z; k = 1; }
                if (d.z > bv) k = 2;
                pc.z = (unsigned char)k;
            }
            {
                int k = 0; float bv = a.w;
                if (b.w > bv) { bv = b.w; k = 1; }
                if (d.w > bv) k = 2;
                pc.w = (unsigned char)k;
            }
            lb.x = (unsigned char)L.x; lb.y = (unsigned char)L.y;
            lb.z = (unsigned char)L.z; lb.w = (unsigned char)L.w;
            *(uchar4*)&pmap[q * 4] = pc;
            *(uchar4*)&lmap[q * 4] = lb;
        }
    }
    __syncthreads();

    // pass 1: 4-way segmented per-column 1-D sweeps.
    // 768 tasks = dir(2) x seg(4) x col(96), 24 serial iters each.
    if (tid < 2 * NSEG * WW) {
        const int col = tid % WW;
        const int seg = (tid / WW) & (NSEG - 1);
        const int dirIdx = tid / (NSEG * WW);
        const int r0 = seg * SEGROWS;
        if (dirIdx == 0) {              // forward (top -> down)
            int last = -1000;
            #pragma unroll 4
            for (int k = 0; k < SEGROWS; k++) {
                int r = r0 + k;
                if (tmapS[r * WW + col] == j) last = r;
                gF[r * WW + col] = (unsigned char)min(r - last, 255);
            }
            lastSet[seg * WW + col] = last;
        } else {                        // backward (bottom -> up)
            int first = 1000;
            #pragma unroll 4
            for (int k = SEGROWS - 1; k >= 0; k--) {
                int r = r0 + k;
                if (tmapS[r * WW + col] == j) first = r;
                gB[r * WW + col] = (unsigned char)min(first - r, 255);
            }
            firstSet[seg * WW + col] = first;
        }
    }
    __syncthreads();

    // per-column prefix-max of lastSet / suffix-min of firstSet (4 iters)
    if (tid < WW) {
        const int col = tid;
        int pm = -1000;
        #pragma unroll
        for (int s = 0; s < NSEG; s++) {
            pmArr[s * WW + col] = pm;
            pm = max(pm, lastSet[s * WW + col]);
        }
    } else if (tid < 2 * WW) {
        const int col = tid - WW;
        int fm = 1000;
        #pragma unroll
        for (int s = NSEG - 1; s >= 0; s--) {
            sfArr[s * WW + col] = fm;
            fm = min(fm, firstSet[s * WW + col]);
        }
    }
    __syncthreads();

    // merge: exact 1-D column distance with cross-segment fix, squared (9 iters)
    for (int p = tid; p < NPIX; p += THREADS) {
        int r = p / WW;
        int cc = p - r * WW;
        int s = r / SEGROWS;
        int d = min((int)gF[p], (int)gB[p]);
        d = min(d, r - pmArr[s * WW + cc]);
        d = min(d, sfArr[s * WW + cc] - r);
        d = min(d, 255);
        g[p] = (unsigned short)(d * d);
    }
    __syncthreads();

    // pass 2: per source pixel, min over columns. 9 exact iterations ->
    // warp-uniform loop, match_any legal.
    int mx_loc = 0;
    for (int p = tid; p < NPIX; p += THREADS) {
        int r = p / WW;
        int cc = p - r * WW;
        bool valid = (smapS[p] == j);
        int best = -1;
        if (valid) {
            const unsigned short* grow = g + r * WW;
            best = grow[cc];
            if (best > 1) {
                // unconditional window dc=1..3 (addresses independent of best)
                int v;
                v = 1 + ((cc - 1 >= 0) ? (int)grow[cc - 1] : 0x7fff); best = min(best, v);
                v = 1 + ((cc + 1 < WW) ? (int)grow[cc + 1] : 0x7fff); best = min(best, v);
                v = 4 + ((cc - 2 >= 0) ? (int)grow[cc - 2] : 0x7fff); best = min(best, v);
                v = 4 + ((cc + 2 < WW) ? (int)grow[cc + 2] : 0x7fff); best = min(best, v);
                v = 9 + ((cc - 3 >= 0) ? (int)grow[cc - 3] : 0x7fff); best = min(best, v);
                v = 9 + ((cc + 3 < WW) ? (int)grow[cc + 3] : 0x7fff); best = min(best, v);
                for (int dc = 4; dc < WW; dc++) {
                    int d2 = dc * dc;
                    if (d2 >= best) break;
                    int cl = cc - dc, cr = cc + dc;
                    if (cl >= 0) { int vv = d2 + (int)grow[cl]; if (vv < best) best = vv; }
                    if (cr < WW) { int vv = d2 + (int)grow[cr]; if (vv < best) best = vv; }
                }
            }
        }
        // warp-aggregate equal bins: one atomic per distinct value per warp
        unsigned grp = __match_any_sync(FULLMASK, best);
        if (valid) {
            if (best < HCAP) {
                if (lane == __ffs(grp) - 1) atomicAdd(&hist[best], __popc(grp));
                mx_loc = max(mx_loc, best);
            } else {
                int pos = atomicAdd(&g_ovf_cnt[c], 1);
                g_ovf[c][pos] = (unsigned short)min(best, 65535);
            }
        }
    }
    __syncthreads();

    // reduction: n, sum(sqrt(d2)), max — shfl tree then cross-warp
    int n_loc = hist[tid];                     // HCAP == THREADS: 1 iter
    float sum_loc = n_loc ? (float)n_loc * sqrtf((float)tid) : 0.f;
    #pragma unroll
    for (int off = 16; off; off >>= 1) {
        n_loc += __shfl_down_sync(FULLMASK, n_loc, off);
        sum_loc += __shfl_down_sync(FULLMASK, sum_loc, off);
        mx_loc = max(mx_loc, __shfl_down_sync(FULLMASK, mx_loc, off));
    }
    if (lane == 0) { s_n[wid] = n_loc; s_sum[wid] = sum_loc; s_mx[wid] = mx_loc; }
    __syncthreads();
    if (wid == 0) {
        int n2 = s_n[lane];
        float sm2 = s_sum[lane];
        int mx2 = s_mx[lane];
        #pragma unroll
        for (int off = 16; off; off >>= 1) {
            n2 += __shfl_down_sync(FULLMASK, n2, off);
            sm2 += __shfl_down_sync(FULLMASK, sm2, off);
            mx2 = max(mx2, __shfl_down_sync(FULLMASK, mx2, off));
        }
        if (lane == 0) { s_n[0] = n2; s_sum[0] = sm2; s_mx[0] = mx2; }
    }
    __syncthreads();

    // stats: warp 0 cooperative percentile scan, lane 0 finishes
    if (wid == 0) {
        const int n_hist = s_n[0];
        const int maxd2 = s_mx[0];
        const int m = g_ovf_cnt[c];      // overflow entries (expected 0)
        const int n = n_hist + m;
        float vlo = 0.f, vhi = 0.f;
        int lo = 0, hi = 0;
        float frac = 0.f;
        bool gotlo = false, gothi = false;
        if (n > 0) {
            float pos = 0.95f * (float)(n - 1);
            lo = (int)floorf(pos);
            hi = (int)ceilf(pos);
            frac = pos - (float)lo;
            int base = 0;
            for (int b0 = 0; b0 <= maxd2 && !gothi; b0 += 32) {
                int bb = b0 + lane;
                int h = (bb < HCAP) ? hist[bb] : 0;
                int cum = h;
                #pragma unroll
                for (int off = 1; off < 32; off <<= 1) {
                    int v = __shfl_up_sync(FULLMASK, cum, off);
                    if (lane >= off) cum += v;
                }
                int ct = base + cum;
                unsigned mlo = __ballot_sync(FULLMASK, ct > lo);
                if (!gotlo && mlo) { vlo = sqrtf((float)(b0 + __ffs(mlo) - 1)); gotlo = true; }
                unsigned mhi = __ballot_sync(FULLMASK, ct > hi);
                if (!gothi && mhi) { vhi = sqrtf((float)(b0 + __ffs(mhi) - 1)); gothi = true; }
                base += __shfl_sync(FULLMASK, cum, 31);
            }
        }
        if (lane == 0) {
            float sum = s_sum[0];
            if (m > 0) {                 // exact slow path, correctness only
                for (int a = 0; a < m - 1; a++) {
                    int mi = a;
                    for (int b = a + 1; b < m; b++)
                        if (g_ovf[c][b] < g_ovf[c][mi]) mi = b;
                    unsigned short t = g_ovf[c][a];
                    g_ovf[c][a] = g_ovf[c][mi];
                    g_ovf[c][mi] = t;
                }
                for (int a = 0; a < m; a++) sum += sqrtf((float)g_ovf[c][a]);
            }
            float mx = 0.f, mean = 0.f, pcl = 0.f;
            if (n > 0) {
                int truemax = (m > 0) ? (int)g_ovf[c][m - 1] : maxd2;
                mx = sqrtf((float)truemax);
                mean = sum / (float)n;
                if (!gotlo) vlo = sqrtf((float)g_ovf[c][lo - n_hist]);
                if (!gothi) vhi = sqrtf((float)g_ovf[c][hi - n_hist]);
                pcl = vlo * (1.0f - frac) + vhi * frac;
            }
            g_stats[c][0] = mx;
            g_stats[c][1] = mean;
            g_stats[c][2] = pcl;
            __threadfence();
            int t = atomicAdd(&g_done, 1);
            s_last = (t == NCOMBO - 1) ? 1 : 0;
        }
    }
    __syncthreads();

    // last block assembles the output
    if (s_last && tid == 0) {
        __threadfence();
        g_done = 0;  // reset for next graph replay
        float st[NCOMBO * 3];
        #pragma unroll
        for (int k = 0; k < NCOMBO * 3 / 4; k++)
            ((float4*)st)[k] = ((const float4*)&g_stats[0][0])[k];
        float M[3][5] = {{0}}, F[3][5] = {{0}}, R[3][5] = {{0}};
        for (int bi = 0; bi < BATCH; bi++) {
            for (int jj = 0; jj < 2; jj++) {
                int jc = jj + 1;
                int cf = (bi << 2) | (jj << 1);
                int cr = cf | 1;
                float fmx = st[cf * 3 + 0], rmx = st[cr * 3 + 0];
                float fme = st[cf * 3 + 1], rme = st[cr * 3 + 1];
                float fp  = st[cf * 3 + 2], rp  = st[cr * 3 + 2];
                F[0][jc] += fmx; R[0][jc] += rmx; M[0][jc] += fmaxf(fmx, rmx);
                F[1][jc] += fme; R[1][jc] += rme; M[1][jc] += fmaxf(fme, rme);
                // faithful to source bug: FHD gets both directions' percentiles,
                // RHD percentile row stays zero
                F[2][jc] += fp + rp;
                M[2][jc] += fmaxf(fp, rp);
            }
        }
        float* mats[3] = {&M[0][0], &F[0][0], &R[0][0]};
        for (int t2 = 0; t2 < 3; t2++) {
            float* X = mats[t2];
            for (int r = 0; r < 3; r++) {
                for (int c2 = 0; c2 < 3; c2++) X[r * 5 + c2] *= 0.25f;  // / batch
                X[r * 5 + 3] = (X[r * 5 + 0] + X[r * 5 + 1] + X[r * 5 + 2]) / 3.0f;
                X[r * 5 + 4] = (X[r * 5 + 1] + X[r * 5 + 2]) * 0.5f;
            }
            for (int k = 0; k < 15; k++) out[t2 * 15 + k] = X[k];
        }
    }
}

// ---------------------------------------------------------------------------
extern "C" void kernel_launch(void* const* d_in, const int* in_sizes, int n_in,
                              void* d_out, int out_size) {
    const float* preds = (const float*)d_in[0];
    const int* labels = (const int*)d_in[1];
    float* out = (float*)d_out;

    cudaFuncSetAttribute(hausdorff_kernel,
                         cudaFuncAttributeMaxDynamicSharedMemorySize, SMEM_BYTES);

    hausdorff_kernel<<<NCOMBO, THREADS, SMEM_BYTES>>>(preds, labels, out);
}

// round 9
// speedup vs baseline: 2.5644x; 1.1400x over previous
#include <cuda_runtime.h>
#include <math.h>

#define BATCH 4
#define NCLS 3
#define HH 96
#define WW 96
#define NPIX (HH * WW)           // 9216
#define NCOMBO 16                // batch(4) x class(2) x dir(2)
#define HCAP 1024                // histogram bins; d^2 >= HCAP -> overflow list
#define THREADS 1024
#define NWARP (THREADS / 32)     // 32
#define NSEG 4
#define SEGROWS (HH / NSEG)      // 24
#define RS 4                     // row-slices per combo
#define SLICEROWS (HH / RS)      // 24
#define SLICEPIX (SLICEROWS * WW)// 2304
#define FULLMASK 0xffffffffu

// cross-kernel state
__device__ int g_hist[NCOMBO][HCAP];           // global histograms (zeroed by prep)
__device__ float g_stats[NCOMBO][3];           // {max, mean, percentile}
__device__ int g_done = 0;                     // last-block-done counter
__device__ int g_ovf_cnt[NCOMBO];
__device__ unsigned short g_ovf[NCOMBO][NPIX]; // overflow d^2 (expected unused)
__device__ unsigned char g_pred[BATCH][NPIX];  // argmax class map
__device__ unsigned char g_lab[BATCH][NPIX];   // label class map

// ---------------------------------------------------------------------------
// Kernel 1 (prep): zero histograms/counters + build byte maps once per batch.
// grid 16 x 1024: 16384 threads == NCOMBO*HCAP bins; 9216 quad tasks.
// ---------------------------------------------------------------------------
__global__ __launch_bounds__(THREADS)
void prep_kernel(const float* __restrict__ preds,
                 const int* __restrict__ labels) {
    int t = blockIdx.x * THREADS + threadIdx.x;
    (&g_hist[0][0])[t] = 0;                    // exactly one bin per thread
    if (t < NCOMBO) g_ovf_cnt[t] = 0;

    const int QPB = NPIX / 4;                  // 2304 quads per batch elem
    if (t < BATCH * QPB) {
        int i = t / QPB;
        int q = t - i * QPB;
        const float* base = preds + (size_t)i * NCLS * NPIX;
        float4 a = __ldg((const float4*)base + q);
        float4 b = __ldg((const float4*)(base + NPIX) + q);
        float4 d = __ldg((const float4*)(base + 2 * NPIX) + q);
        int4 L = __ldg((const int4*)(labels + i * NPIX) + q);
        uchar4 pc, lb;
        {
            int k = 0; float bv = a.x;
            if (b.x > bv) { bv = b.x; k = 1; }
            if (d.x > bv) k = 2;
            pc.x = (unsigned char)k;
        }
        {
            int k = 0; float bv = a.y;
            if (b.y > bv) { bv = b.y; k = 1; }
            if (d.y > bv) k = 2;
            pc.y = (unsigned char)k;
        }
        {
            int k = 0; float bv = a.z;
            if (b.z > bv) { bv = b.z; k = 1; }
            if (d.z > bv) k = 2;
            pc.z = (unsigned char)k;
        }
        {
            int k = 0; float bv = a.w;
            if (b.w > bv) { bv = b.w; k = 1; }
            if (d.w > bv) k = 2;
            pc.w = (unsigned char)k;
        }
        lb.x = (unsigned char)L.x; lb.y = (unsigned char)L.y;
        lb.z = (unsigned char)L.z; lb.w = (unsigned char)L.w;
        *(uchar4*)&g_pred[i][q * 4] = pc;
        *(uchar4*)&g_lab[i][q * 4] = lb;
    }
}

// ---------------------------------------------------------------------------
// Kernel 2 (field): 64 blocks = 16 combos x 4 row-slices.
// Recomputes cheap column sweeps per block; merge + pass-2 only on its slice;
// warp-aggregated RED.ADD into the global per-combo histogram.
//
// Dynamic smem:
//   ushort g[NPIX]         18432 B  (only slice rows written/read)
//   uchar  gF[NPIX]         9216 B
//   uchar  gB[NPIX]         9216 B
//   uchar  smapS[NPIX]      9216 B
//   uchar  tmapS[NPIX]      9216 B
//   int    lastSet/firstSet/pmArr/sfArr [4][96] x4 = 6144 B
// ---------------------------------------------------------------------------
#define SMEM_K1 (NPIX * 2 + NPIX * 4 + 4 * NSEG * WW * 4)

__global__ __launch_bounds__(THREADS, 1)
void field_kernel() {
    extern __shared__ char smem[];
    unsigned short* g = (unsigned short*)smem;
    unsigned char* gF = (unsigned char*)(g + NPIX);
    unsigned char* gB = gF + NPIX;
    unsigned char* smapS = gB + NPIX;
    unsigned char* tmapS = smapS + NPIX;
    int* lastSet = (int*)(tmapS + NPIX);       // [NSEG][WW]
    int* firstSet = lastSet + NSEG * WW;
    int* pmArr = firstSet + NSEG * WW;
    int* sfArr = pmArr + NSEG * WW;

    const int c = blockIdx.x / RS;
    const int slice = blockIdx.x - c * RS;
    const int i = c >> 2;
    const int j = ((c >> 1) & 1) + 1;
    const int dir = c & 1;
    const int tid = threadIdx.x;
    const int lane = tid & 31;

    // copy byte maps from global (L2-hot) into smem, uint4 = 16 B/thread, 1 iter
    {
        const uint4* sm = (const uint4*)(dir == 0 ? g_pred[i] : g_lab[i]);
        const uint4* tm = (const uint4*)(dir == 0 ? g_lab[i] : g_pred[i]);
        uint4* ds = (uint4*)smapS;
        uint4* dt = (uint4*)tmapS;
        for (int q = tid; q < NPIX / 16; q += THREADS) {
            ds[q] = __ldg(&sm[q]);
            dt[q] = __ldg(&tm[q]);
        }
    }
    __syncthreads();

    // pass 1: 4-way segmented per-column 1-D sweeps (768 tasks, 24 iters)
    if (tid < 2 * NSEG * WW) {
        const int col = tid % WW;
        const int seg = (tid / WW) & (NSEG - 1);
        const int dirIdx = tid / (NSEG * WW);
        const int r0 = seg * SEGROWS;
        if (dirIdx == 0) {              // forward (top -> down)
            int last = -1000;
            #pragma unroll 4
            for (int k = 0; k < SEGROWS; k++) {
                int r = r0 + k;
                if (tmapS[r * WW + col] == j) last = r;
                gF[r * WW + col] = (unsigned char)min(r - last, 255);
            }
            lastSet[seg * WW + col] = last;
        } else {                        // backward (bottom -> up)
            int first = 1000;
            #pragma unroll 4
            for (int k = SEGROWS - 1; k >= 0; k--) {
                int r = r0 + k;
                if (tmapS[r * WW + col] == j) first = r;
                gB[r * WW + col] = (unsigned char)min(first - r, 255);
            }
            firstSet[seg * WW + col] = first;
        }
    }
    __syncthreads();

    // per-column prefix-max of lastSet / suffix-min of firstSet (4 iters)
    if (tid < WW) {
        const int col = tid;
        int pm = -1000;
        #pragma unroll
        for (int s = 0; s < NSEG; s++) {
            pmArr[s * WW + col] = pm;
            pm = max(pm, lastSet[s * WW + col]);
        }
    } else if (tid < 2 * WW) {
        const int col = tid - WW;
        int fm = 1000;
        #pragma unroll
        for (int s = NSEG - 1; s >= 0; s--) {
            sfArr[s * WW + col] = fm;
            fm = min(fm, firstSet[s * WW + col]);
        }
    }
    __syncthreads();

    const int p0 = slice * SLICEPIX;

    // merge: exact 1-D column distance for slice rows only (2.25 iters)
    for (int p = p0 + tid; p < p0 + SLICEPIX; p += THREADS) {
        int r = p / WW;
        int cc = p - r * WW;
        int s = r / SEGROWS;
        int d = min((int)gF[p], (int)gB[p]);
        d = min(d, r - pmArr[s * WW + cc]);
        d = min(d, sfArr[s * WW + cc] - r);
        d = min(d, 255);
        g[p] = (unsigned short)(d * d);
    }
    __syncthreads();

    // pass 2: slice rows only (2.25 iters, warp-uniform -> match_any legal)
    for (int p = p0 + tid; p < p0 + SLICEPIX; p += THREADS) {
        int r = p / WW;
        int cc = p - r * WW;
        bool valid = (smapS[p] == j);
        int best = -1;
        if (valid) {
            const unsigned short* grow = g + r * WW;
            best = grow[cc];
            if (best > 1) {
                int v;
                v = 1 + ((cc - 1 >= 0) ? (int)grow[cc - 1] : 0x7fff); best = min(best, v);
                v = 1 + ((cc + 1 < WW) ? (int)grow[cc + 1] : 0x7fff); best = min(best, v);
                v = 4 + ((cc - 2 >= 0) ? (int)grow[cc - 2] : 0x7fff); best = min(best, v);
                v = 4 + ((cc + 2 < WW) ? (int)grow[cc + 2] : 0x7fff); best = min(best, v);
                v = 9 + ((cc - 3 >= 0) ? (int)grow[cc - 3] : 0x7fff); best = min(best, v);
                v = 9 + ((cc + 3 < WW) ? (int)grow[cc + 3] : 0x7fff); best = min(best, v);
                for (int dc = 4; dc < WW; dc++) {
                    int d2 = dc * dc;
                    if (d2 >= best) break;
                    int cl = cc - dc, cr = cc + dc;
                    if (cl >= 0) { int vv = d2 + (int)grow[cl]; if (vv < best) best = vv; }
                    if (cr < WW) { int vv = d2 + (int)grow[cr]; if (vv < best) best = vv; }
                }
            }
        }
        // warp-aggregate equal bins: one global RED per distinct value per warp
        unsigned grp = __match_any_sync(FULLMASK, best);
        if (valid) {
            if (best < HCAP) {
                if (lane == __ffs(grp) - 1) atomicAdd(&g_hist[c][best], __popc(grp));
            } else {
                int pos = atomicAdd(&g_ovf_cnt[c], 1);
                g_ovf[c][pos] = (unsigned short)min(best, 65535);
            }
        }
    }
}

// ---------------------------------------------------------------------------
// Kernel 3 (stats): one block per combo; last finishing block assembles output.
// ---------------------------------------------------------------------------
__global__ __launch_bounds__(THREADS, 1)
void stats_kernel(float* __restrict__ out) {
    __shared__ int sh_hist[HCAP];
    __shared__ int s_n[NWARP];
    __shared__ float s_sum[NWARP];
    __shared__ int s_mx[NWARP];
    __shared__ int s_last;

    const int c = blockIdx.x;
    const int tid = threadIdx.x;
    const int lane = tid & 31;
    const int wid = tid >> 5;

    int h = __ldg(&g_hist[c][tid]);            // 1 iter (HCAP == THREADS)
    sh_hist[tid] = h;
    int n_loc = h;
    float sum_loc = h ? (float)h * sqrtf((float)tid) : 0.f;
    int mx_loc = h ? tid : 0;
    #pragma unroll
    for (int off = 16; off; off >>= 1) {
        n_loc += __shfl_down_sync(FULLMASK, n_loc, off);
        sum_loc += __shfl_down_sync(FULLMASK, sum_loc, off);
        mx_loc = max(mx_loc, __shfl_down_sync(FULLMASK, mx_loc, off));
    }
    if (lane == 0) { s_n[wid] = n_loc; s_sum[wid] = sum_loc; s_mx[wid] = mx_loc; }
    __syncthreads();
    if (wid == 0) {
        int n2 = s_n[lane];
        float sm2 = s_sum[lane];
        int mx2 = s_mx[lane];
        #pragma unroll
        for (int off = 16; off; off >>= 1) {
            n2 += __shfl_down_sync(FULLMASK, n2, off);
            sm2 += __shfl_down_sync(FULLMASK, sm2, off);
            mx2 = max(mx2, __shfl_down_sync(FULLMASK, mx2, off));
        }
        if (lane == 0) { s_n[0] = n2; s_sum[0] = sm2; s_mx[0] = mx2; }
    }
    __syncthreads();

    // warp 0 cooperative percentile scan, lane 0 finishes
    if (wid == 0) {
        const int n_hist = s_n[0];
        const int maxd2 = s_mx[0];
        const int m = g_ovf_cnt[c];      // overflow entries (expected 0)
        const int n = n_hist + m;
        float vlo = 0.f, vhi = 0.f;
        int lo = 0, hi = 0;
        float frac = 0.f;
        bool gotlo = false, gothi = false;
        if (n > 0) {
            float pos = 0.95f * (float)(n - 1);
            lo = (int)floorf(pos);
            hi = (int)ceilf(pos);
            frac = pos - (float)lo;
            int base = 0;
            for (int b0 = 0; b0 <= maxd2 && !gothi; b0 += 32) {
                int bb = b0 + lane;
                int hh = (bb < HCAP) ? sh_hist[bb] : 0;
                int cum = hh;
                #pragma unroll
                for (int off = 1; off < 32; off <<= 1) {
                    int v = __shfl_up_sync(FULLMASK, cum, off);
                    if (lane >= off) cum += v;
                }
                int ct = base + cum;
                unsigned mlo = __ballot_sync(FULLMASK, ct > lo);
                if (!gotlo && mlo) { vlo = sqrtf((float)(b0 + __ffs(mlo) - 1)); gotlo = true; }
                unsigned mhi = __ballot_sync(FULLMASK, ct > hi);
                if (!gothi && mhi) { vhi = sqrtf((float)(b0 + __ffs(mhi) - 1)); gothi = true; }
                base += __shfl_sync(FULLMASK, cum, 31);
            }
        }
        if (lane == 0) {
            float sum = s_sum[0];
            if (m > 0) {                 // exact slow path, correctness only
                for (int a = 0; a < m - 1; a++) {
                    int mi = a;
                    for (int b = a + 1; b < m; b++)
                        if (g_ovf[c][b] < g_ovf[c][mi]) mi = b;
                    unsigned short t = g_ovf[c][a];
                    g_ovf[c][a] = g_ovf[c][mi];
                    g_ovf[c][mi] = t;
                }
                for (int a = 0; a < m; a++) sum += sqrtf((float)g_ovf[c][a]);
            }
            float mx = 0.f, mean = 0.f, pcl = 0.f;
            if (n > 0) {
                int truemax = (m > 0) ? (int)g_ovf[c][m - 1] : maxd2;
                mx = sqrtf((float)truemax);
                mean = sum / (float)n;
                if (!gotlo) vlo = sqrtf((float)g_ovf[c][lo - n_hist]);
                if (!gothi) vhi = sqrtf((float)g_ovf[c][hi - n_hist]);
                pcl = vlo * (1.0f - frac) + vhi * frac;
            }
            g_stats[c][0] = mx;
            g_stats[c][1] = mean;
            g_stats[c][2] = pcl;
            __threadfence();
            int t = atomicAdd(&g_done, 1);
            s_last = (t == NCOMBO - 1) ? 1 : 0;
        }
    }
    __syncthreads();

    // last block assembles the output
    if (s_last && tid == 0) {
        __threadfence();
        g_done = 0;  // reset for next graph replay
        float st[NCOMBO * 3];
        #pragma unroll
        for (int k = 0; k < NCOMBO * 3 / 4; k++)
            ((float4*)st)[k] = ((const float4*)&g_stats[0][0])[k];
        float M[3][5] = {{0}}, F[3][5] = {{0}}, R[3][5] = {{0}};
        for (int bi = 0; bi < BATCH; bi++) {
            for (int jj = 0; jj < 2; jj++) {
                int jc = jj + 1;
                int cf = (bi << 2) | (jj << 1);
                int cr = cf | 1;
                float fmx = st[cf * 3 + 0], rmx = st[cr * 3 + 0];
                float fme = st[cf * 3 + 1], rme = st[cr * 3 + 1];
                float fp  = st[cf * 3 + 2], rp  = st[cr * 3 + 2];
                F[0][jc] += fmx; R[0][jc] += rmx; M[0][jc] += fmaxf(fmx, rmx);
                F[1][jc] += fme; R[1][jc] += rme; M[1][jc] += fmaxf(fme, rme);
                // faithful to source bug: FHD gets both directions' percentiles,
                // RHD percentile row stays zero
                F[2][jc] += fp + rp;
                M[2][jc] += fmaxf(fp, rp);
            }
        }
        float* mats[3] = {&M[0][0], &F[0][0], &R[0][0]};
        for (int t2 = 0; t2 < 3; t2++) {
            float* X = mats[t2];
            for (int r = 0; r < 3; r++) {
                for (int c2 = 0; c2 < 3; c2++) X[r * 5 + c2] *= 0.25f;  // / batch
                X[r * 5 + 3] = (X[r * 5 + 0] + X[r * 5 + 1] + X[r * 5 + 2]) / 3.0f;
                X[r * 5 + 4] = (X[r * 5 + 1] + X[r * 5 + 2]) * 0.5f;
            }
            for (int k = 0; k < 15; k++) out[t2 * 15 + k] = X[k];
        }
    }
}

// ---------------------------------------------------------------------------
extern "C" void kernel_launch(void* const* d_in, const int* in_sizes, int n_in,
                              void* d_out, int out_size) {
    const float* preds = (const float*)d_in[0];
    const int* labels = (const int*)d_in[1];
    float* out = (float*)d_out;

    cudaFuncSetAttribute(field_kernel,
                         cudaFuncAttributeMaxDynamicSharedMemorySize, SMEM_K1);

    prep_kernel<<<NCOMBO, THREADS>>>(preds, labels);
    field_kernel<<<NCOMBO * RS, THREADS, SMEM_K1>>>();
    stats_kernel<<<NCOMBO, THREADS>>>(out);
}